// round 6
// baseline (speedup 1.0000x reference)
#include <cuda_runtime.h>
#include <cstdint>

// ---------------- problem constants ----------------
#define B_    128
#define CIN_  64
#define NF_   16
#define COUT_ 256
#define H_    20
#define W_    20
#define HW_   400
#define K_    1024
#define M_    51200

#define MT      128      // M rows per CTA tile
#define KC      64       // K per chunk = 4 cin x 16 nf
#define NCHUNK  16
#define NTHREADS 512

// ---------------- smem layout (bytes) ----------------
// bias [0, 1024)
// A    [1024,  33792)   2 x (128 rows x 128B)  fp16
// B    [33792, 99328)   2 x (256 rows x 128B)  fp16
#define OFF_A    1024
#define OFF_B    33792
#define SMEM_TOTAL 99328

// ---------------- device scratch ----------------
__device__ float2   g_xpair[B_ * CIN_ * HW_];        // 26.2MB: (x[p], x[p+1])
__device__ uint4    g_combB[NCHUNK * COUT_ * 8];     // 512KB pre-swizzled fp16 images
__device__ uint32_t g_tapO[NF_ * HW_];               // packed byte offsets (2x u16)
__device__ float4   g_tapW[NF_ * HW_];               // remapped pair weights

// ---------------- small helpers ----------------
__device__ __forceinline__ uint32_t smem_u32(const void* p) {
    uint32_t a;
    asm("{ .reg .u64 t; cvta.to.shared.u64 t, %1; cvt.u32.u64 %0, t; }" : "=r"(a) : "l"(p));
    return a;
}
__device__ __forceinline__ uint32_t pack_h2(float lo, float hi) {
    uint32_t u;
    asm("cvt.rn.f16x2.f32 %0, %1, %2;" : "=r"(u) : "f"(hi), "f"(lo));  // {hi, lo}
    return u;
}
__device__ __forceinline__ void ldsm_x4(uint32_t& r0, uint32_t& r1, uint32_t& r2, uint32_t& r3,
                                        uint32_t addr) {
    asm volatile("ldmatrix.sync.aligned.m8n8.x4.shared.b16 {%0,%1,%2,%3}, [%4];"
                 : "=r"(r0), "=r"(r1), "=r"(r2), "=r"(r3) : "r"(addr));
}
__device__ __forceinline__ void mma_f16(float c[4], uint32_t a0, uint32_t a1, uint32_t a2,
                                        uint32_t a3, uint32_t b0, uint32_t b1) {
    asm volatile("mma.sync.aligned.m16n8k16.row.col.f32.f16.f16.f32 "
                 "{%0,%1,%2,%3}, {%4,%5,%6,%7}, {%8,%9}, {%0,%1,%2,%3};"
                 : "+f"(c[0]), "+f"(c[1]), "+f"(c[2]), "+f"(c[3])
                 : "r"(a0), "r"(a1), "r"(a2), "r"(a3), "r"(b0), "r"(b1));
}
__device__ __forceinline__ void cp16(uint32_t dst, const void* src) {
    asm volatile("cp.async.cg.shared.global [%0], [%1], 16;" :: "r"(dst), "l"(src) : "memory");
}

// ---------------- prologue: x -> overlapping pairs ----------------
__global__ void xpair_kernel(const float* __restrict__ x) {
    int t = blockIdx.x * blockDim.x + threadIdx.x;
    if (t >= B_ * CIN_ * HW_) return;
    int p = t % HW_;
    float v0 = x[t];
    float v1 = (p < HW_ - 1) ? x[t + 1] : 0.f;
    g_xpair[t] = make_float2(v0, v1);
}

// ---------------- prologue: tap tables (paired form) ----------------
__global__ void tap_kernel(const float* __restrict__ flow) {
    int t = blockIdx.x * blockDim.x + threadIdx.x;
    if (t >= NF_ * HW_) return;
    int nf = t / HW_;
    int p  = t % HW_;
    int i  = p / W_;
    int j  = p % W_;

    float fx = flow[((nf * H_ + i) * W_ + j) * 2 + 0];
    float fy = flow[((nf * H_ + i) * W_ + j) * 2 + 1];
    float ix = (float)i + fx;
    float iy = (float)j + fy;
    float bxf = floorf(ix), byf = floorf(iy);
    float s = ix - bxf, tt = iy - byf;
    int bx = (int)bxf, by = (int)byf;

    // NOTE: w10 intentionally equals w01 (replicates the reference's bug).
    float w00 = (1.f - s) * (1.f - tt);   // (bx,   by)
    float w01 = s * (1.f - tt);           // (bx+1, by)
    float w10 = s * (1.f - tt);           // (bx,   by+1)
    float w11 = s * tt;                   // (bx+1, by+1)

    int cc0 = min(max(by, 0), W_);     bool cv0 = cc0 < W_;
    int cc1 = min(max(by + 1, 0), W_); bool cv1 = cc1 < W_;
    int cb  = min(max(by, 0), W_ - 2);
    float m0lo = (cv0 && cc0 == cb)     ? 1.f : 0.f;
    float m0hi = (cv0 && cc0 == cb + 1) ? 1.f : 0.f;
    float m1lo = (cv1 && cc1 == cb)     ? 1.f : 0.f;
    float m1hi = (cv1 && cc1 == cb + 1) ? 1.f : 0.f;

    int rr0 = min(max(bx, 0), H_);     bool rv0 = rr0 < H_;
    int rr1 = min(max(bx + 1, 0), H_); bool rv1 = rr1 < H_;
    int r0c = rv0 ? rr0 : 0;
    int r1c = rv1 ? rr1 : 0;

    float u0 = rv0 ? (w00 * m0lo + w10 * m1lo) : 0.f;
    float u1 = rv0 ? (w00 * m0hi + w10 * m1hi) : 0.f;
    float v0 = rv1 ? (w01 * m0lo + w11 * m1lo) : 0.f;
    float v1 = rv1 ? (w01 * m0hi + w11 * m1hi) : 0.f;

    uint32_t o0 = (uint32_t)((r0c * W_ + cb) * 8);   // byte offset into float2 plane
    uint32_t o1 = (uint32_t)((r1c * W_ + cb) * 8);
    g_tapO[nf * HW_ + p] = o0 | (o1 << 16);
    g_tapW[nf * HW_ + p] = make_float4(u0, u1, v0, v1);
}

// ---------------- prologue: comb -> fp16, pre-swizzled chunk images ----------
__global__ void comb_prep(const float* __restrict__ comb) {
    int t = blockIdx.x * blockDim.x + threadIdx.x;
    if (t >= NCHUNK * COUT_) return;
    int kc = t >> 8;
    int o  = t & 255;
    const float* src = comb + o * K_ + kc * KC;
    #pragma unroll
    for (int g = 0; g < 8; g++) {
        float4 a = *(const float4*)(src + g * 8);
        float4 b = *(const float4*)(src + g * 8 + 4);
        uint4 u;
        u.x = pack_h2(a.x, a.y); u.y = pack_h2(a.z, a.w);
        u.z = pack_h2(b.x, b.y); u.w = pack_h2(b.z, b.w);
        g_combB[(kc * COUT_ + o) * 8 + (g ^ (o & 7))] = u;
    }
}

// ---------------- fused kernel ----------------
__global__ __launch_bounds__(NTHREADS, 1)
void mma_kernel(const float* __restrict__ bias, float* __restrict__ out) {
    extern __shared__ char smem[];
    float* sBias = (float*)smem;
    const uint32_t sbase = smem_u32(smem);

    const int tx = threadIdx.x;
    const int m0 = blockIdx.x * MT;

    if (tx < COUT_) sBias[tx] = bias[tx];

    // ---- A-gen ownership: row ml, nf quarter g (4 nf each) ----
    const int ml = tx & 127;
    const int g  = tx >> 7;                  // 0..3
    const int m  = m0 + ml;
    const int p  = m % HW_;
    const char* xpb = (const char*)(g_xpair + (size_t)(m / HW_) * CIN_ * HW_);

    uint32_t tapO[4];
    float4   tapW[4];
    #pragma unroll
    for (int q = 0; q < 4; q++) {
        int nf = g * 4 + q;
        tapO[q] = g_tapO[nf * HW_ + p];
        tapW[q] = g_tapW[nf * HW_ + p];
    }

    const int lane  = tx & 31;
    const int wid   = tx >> 5;               // 0..15
    const int warpM = wid & 3;               // 4 M-groups of 32
    const int warpN = wid >> 2;              // 4 N-groups of 64
    const uint32_t swx = (uint32_t)((ml & 7) << 4);

    float acc[2][8][4];
    #pragma unroll
    for (int i = 0; i < 2; i++)
        #pragma unroll
        for (int j = 0; j < 8; j++)
            #pragma unroll
            for (int q = 0; q < 4; q++) acc[i][j][q] = 0.f;

    auto produce = [&](int kc) {
        // B: async copy of pre-swizzled fp16 image (32KB over 512 threads)
        {
            const char* src = (const char*)(g_combB + (size_t)kc * COUT_ * 8);
            uint32_t dst = sbase + OFF_B + (kc & 1) * 32768;
            #pragma unroll
            for (int i = 0; i < 4; i++)
                cp16(dst + (i * 512 + tx) * 16, src + (i * 512 + tx) * 16);
            asm volatile("cp.async.commit_group;" ::: "memory");
        }
        // A: paired gathers, 4 nf x 4 cin = 16 values
        {
            const char* xc = xpb + (size_t)(kc * 4) * (HW_ * 8);
            uint32_t abase = sbase + OFF_A + (kc & 1) * 16384 + ml * 128;
            #pragma unroll
            for (int cl = 0; cl < 4; cl++) {
                const char* pl = xc + cl * (HW_ * 8);
                float val[4];
                #pragma unroll
                for (int q = 0; q < 4; q++) {
                    uint32_t pk = tapO[q];
                    float4 w = tapW[q];
                    float2 lo = *(const float2*)(pl + (pk & 0xFFFFu));
                    float2 hi = *(const float2*)(pl + (pk >> 16));
                    float v = lo.x * w.x;
                    v = fmaf(lo.y, w.y, v);
                    v = fmaf(hi.x, w.z, v);
                    v = fmaf(hi.y, w.w, v);
                    val[q] = v;
                }
                // k word = cl*16 + g*4 + q  -> byte group cl*32 + g*8 (8B store)
                uint2 u;
                u.x = pack_h2(val[0], val[1]);
                u.y = pack_h2(val[2], val[3]);
                uint32_t addr = abase + (((uint32_t)(cl * 32 + g * 8)) ^ swx);
                asm volatile("st.shared.v2.b32 [%0], {%1,%2};"
                             :: "r"(addr), "r"(u.x), "r"(u.y) : "memory");
            }
        }
    };

    // ldmatrix address: 8x8 tiles at (rowBase, kByte), canonical x4 lane map
    auto lm_addr = [&](uint32_t base, int rowBase, int kByte) -> uint32_t {
        int r  = rowBase + (lane & 7) + 8 * ((lane >> 3) & 1);
        int cb = kByte + 16 * (lane >> 4);
        return base + r * 128 + (uint32_t)(cb ^ ((r & 7) << 4));
    };

    produce(0);
    asm volatile("cp.async.wait_group 0;" ::: "memory");
    __syncthreads();

    #pragma unroll 1
    for (int kc = 0; kc < NCHUNK; kc++) {
        if (kc + 1 < NCHUNK) produce(kc + 1);

        const uint32_t aBuf = sbase + OFF_A + (kc & 1) * 16384;
        const uint32_t bBuf = sbase + OFF_B + (kc & 1) * 32768;

        #pragma unroll
        for (int s = 0; s < 4; s++) {
            const int kB = s * 32;
            uint32_t bb[4][4];
            #pragma unroll
            for (int jn = 0; jn < 4; jn++)
                ldsm_x4(bb[jn][0], bb[jn][1], bb[jn][2], bb[jn][3],
                        lm_addr(bBuf, warpN * 64 + jn * 16, kB));
            #pragma unroll
            for (int wm = 0; wm < 2; wm++) {
                uint32_t a0, a1, a2, a3;
                ldsm_x4(a0, a1, a2, a3, lm_addr(aBuf, warpM * 32 + wm * 16, kB));
                #pragma unroll
                for (int jn = 0; jn < 4; jn++) {
                    mma_f16(acc[wm][jn * 2 + 0], a0, a1, a2, a3, bb[jn][0], bb[jn][2]);
                    mma_f16(acc[wm][jn * 2 + 1], a0, a1, a2, a3, bb[jn][1], bb[jn][3]);
                }
            }
        }
        asm volatile("cp.async.wait_group 0;" ::: "memory");
        __syncthreads();
    }

    // ---- epilogue ----
    const int r = lane >> 2;
    const int c = lane & 3;
    #pragma unroll
    for (int wm = 0; wm < 2; wm++) {
        int mr0 = m0 + warpM * 32 + wm * 16 + r;
        int mr1 = mr0 + 8;
        int b0i = mr0 / HW_, p0 = mr0 - b0i * HW_;
        int b1i = mr1 / HW_, p1 = mr1 - b1i * HW_;
        float* o0 = out + (size_t)b0i * COUT_ * HW_ + p0;
        float* o1 = out + (size_t)b1i * COUT_ * HW_ + p1;
        #pragma unroll
        for (int j = 0; j < 8; j++) {
            int n0 = warpN * 64 + (j >> 1) * 16 + (j & 1) * 8 + 2 * c;
            float bz0 = sBias[n0], bz1 = sBias[n0 + 1];
            o0[(size_t)n0 * HW_]       = acc[wm][j][0] + bz0;
            o0[(size_t)(n0 + 1) * HW_] = acc[wm][j][1] + bz1;
            o1[(size_t)n0 * HW_]       = acc[wm][j][2] + bz0;
            o1[(size_t)(n0 + 1) * HW_] = acc[wm][j][3] + bz1;
        }
    }
}

extern "C" void kernel_launch(void* const* d_in, const int* in_sizes, int n_in,
                              void* d_out, int out_size) {
    const float* x    = (const float*)d_in[0];
    const float* flow = (const float*)d_in[1];
    const float* comb = (const float*)d_in[2];
    const float* bias = (const float*)d_in[3];
    float* out = (float*)d_out;

    cudaFuncSetAttribute(mma_kernel,
                         cudaFuncAttributeMaxDynamicSharedMemorySize, SMEM_TOTAL);

    xpair_kernel<<<(B_ * CIN_ * HW_ + 255) / 256, 256>>>(x);
    tap_kernel<<<(NF_ * HW_ + 255) / 256, 256>>>(flow);
    comb_prep<<<(NCHUNK * COUT_ + 255) / 256, 256>>>(comb);
    mma_kernel<<<M_ / MT, NTHREADS, SMEM_TOTAL>>>(bias, out);
}

// round 7
// speedup vs baseline: 1.4341x; 1.4341x over previous
#include <cuda_runtime.h>
#include <cuda_fp16.h>
#include <cstdint>

// ---------------- problem constants ----------------
#define B_    128
#define CIN_  64
#define NF_   16
#define COUT_ 256
#define H_    20
#define W_    20
#define HW_   400
#define K_    1024
#define M_    51200

#define MT      64       // M rows per CTA tile
#define KC      64       // K per chunk = 64 cin of one nf  (chunk kc <-> nf)
#define NCHUNK  16
#define NSTAGE  4
#define NTHREADS 256

// ---------------- smem layout (bytes) ----------------
// mbar  [0, 64)    full[s]=s*8, empty[s]=32+s*8
// A     [1024,  33792)   4 x (64 rows x 128B)  fp16
// B     [33792, 164864)  4 x (256 rows x 128B) fp16
#define OFF_A    1024
#define OFF_B    33792
#define SMEM_TOTAL 164864

// ---------------- device scratch ----------------
__device__ __half g_xT[B_ * HW_ * CIN_];          // 6.55MB: [b][p][cin] fp16
__device__ uint4  g_combB[NCHUNK * COUT_ * 8];    // 512KB pre-swizzled fp16 B images
__device__ uint4  g_tapO4[NF_ * HW_];             // 4 byte-offsets (rows) into xT slab
__device__ float4 g_tapW4[NF_ * HW_];             // 4 tap weights

// ---------------- helpers ----------------
__device__ __forceinline__ uint32_t smem_u32(const void* p) {
    uint32_t a;
    asm("{ .reg .u64 t; cvta.to.shared.u64 t, %1; cvt.u32.u64 %0, t; }" : "=r"(a) : "l"(p));
    return a;
}
__device__ __forceinline__ uint32_t pack_h2(float lo, float hi) {
    uint32_t u;
    asm("cvt.rn.f16x2.f32 %0, %1, %2;" : "=r"(u) : "f"(hi), "f"(lo));
    return u;
}
__device__ __forceinline__ void ldsm_x4(uint32_t& r0, uint32_t& r1, uint32_t& r2, uint32_t& r3,
                                        uint32_t addr) {
    asm volatile("ldmatrix.sync.aligned.m8n8.x4.shared.b16 {%0,%1,%2,%3}, [%4];"
                 : "=r"(r0), "=r"(r1), "=r"(r2), "=r"(r3) : "r"(addr));
}
__device__ __forceinline__ void mma_f16(float c[4], uint32_t a0, uint32_t a1, uint32_t a2,
                                        uint32_t a3, uint32_t b0, uint32_t b1) {
    asm volatile("mma.sync.aligned.m16n8k16.row.col.f32.f16.f16.f32 "
                 "{%0,%1,%2,%3}, {%4,%5,%6,%7}, {%8,%9}, {%0,%1,%2,%3};"
                 : "+f"(c[0]), "+f"(c[1]), "+f"(c[2]), "+f"(c[3])
                 : "r"(a0), "r"(a1), "r"(a2), "r"(a3), "r"(b0), "r"(b1));
}
__device__ __forceinline__ void cp16(uint32_t dst, const void* src) {
    asm volatile("cp.async.cg.shared.global [%0], [%1], 16;" :: "r"(dst), "l"(src) : "memory");
}
#define MBARRIER_INIT(addr, cnt) \
    asm volatile("mbarrier.init.shared.b64 [%0], %1;" :: "r"((uint32_t)(addr)), "r"((uint32_t)(cnt)) : "memory")
#define MBARRIER_ARRIVE(addr) \
    asm volatile("mbarrier.arrive.shared.b64 _, [%0];" :: "r"((uint32_t)(addr)) : "memory")
#define MBARRIER_WAIT_PARITY(addr, par) do {                                        \
    uint32_t _m = (uint32_t)(addr); uint32_t _p = (uint32_t)(par); uint32_t _d;     \
    asm volatile("{\n\t.reg .pred p;\n\t"                                           \
        "mbarrier.try_wait.parity.shared.b64 p, [%1], %2;\n\t"                      \
        "selp.b32 %0, 1, 0, p;\n\t}" : "=r"(_d) : "r"(_m), "r"(_p) : "memory");     \
    if (!_d) {                                                                      \
        asm volatile("{\n\t.reg .pred P1;\n\t"                                      \
        "WL_%=:\n\t"                                                                \
        "mbarrier.try_wait.parity.shared.b64 P1, [%0], %1;\n\t"                     \
        "@P1 bra.uni WD_%=;\n\tbra.uni WL_%=;\n\tWD_%=:\n\t}"                       \
        :: "r"(_m), "r"(_p) : "memory");                                            \
    }                                                                               \
} while (0)

// ---------------- prologue: x -> xT[b][p][cin] fp16 ----------------
__global__ void xt_kernel(const float* __restrict__ x) {
    int t = blockIdx.x * blockDim.x + threadIdx.x;
    if (t >= B_ * HW_) return;
    int b = t / HW_;
    int p = t % HW_;
    const float* src = x + (size_t)b * CIN_ * HW_ + p;
    uint32_t row[32];
    #pragma unroll
    for (int c = 0; c < 32; c++)
        row[c] = pack_h2(src[(2 * c) * HW_], src[(2 * c + 1) * HW_]);
    uint4* dst = (uint4*)(g_xT + (size_t)t * CIN_);
    #pragma unroll
    for (int q = 0; q < 8; q++)
        dst[q] = make_uint4(row[q * 4], row[q * 4 + 1], row[q * 4 + 2], row[q * 4 + 3]);
}

// ---------------- prologue: tap tables (4-tap form) ----------------
__global__ void tap_kernel(const float* __restrict__ flow) {
    int t = blockIdx.x * blockDim.x + threadIdx.x;
    if (t >= NF_ * HW_) return;
    int nf = t / HW_;
    int p  = t % HW_;
    int i  = p / W_;
    int j  = p % W_;

    float fx = flow[((nf * H_ + i) * W_ + j) * 2 + 0];
    float fy = flow[((nf * H_ + i) * W_ + j) * 2 + 1];
    float ix = (float)i + fx;
    float iy = (float)j + fy;
    float bxf = floorf(ix), byf = floorf(iy);
    float s = ix - bxf, tt = iy - byf;
    int bx = (int)bxf, by = (int)byf;

    // NOTE: w10 intentionally equals w01 (replicates the reference's bug).
    float w00 = (1.f - s) * (1.f - tt);
    float w01 = s * (1.f - tt);
    float w10 = s * (1.f - tt);
    float w11 = s * tt;

    int   rs[4] = {bx, bx + 1, bx, bx + 1};
    int   cs[4] = {by, by, by + 1, by + 1};
    float ws[4] = {w00, w01, w10, w11};

    uint32_t o[4];
    float    w[4];
    #pragma unroll
    for (int k = 0; k < 4; k++) {
        int r = min(max(rs[k], 0), H_);
        int c = min(max(cs[k], 0), W_);
        if (r == H_ || c == W_) { o[k] = 0; w[k] = 0.f; }       // zero-pad tap
        else                    { o[k] = (uint32_t)((r * W_ + c) * 128); w[k] = ws[k]; }
    }
    g_tapO4[nf * HW_ + p] = make_uint4(o[0], o[1], o[2], o[3]);
    g_tapW4[nf * HW_ + p] = make_float4(w[0], w[1], w[2], w[3]);
}

// ---------------- prologue: comb -> fp16 chunk images, k = nf*64 + cin -------
__global__ void comb_prep(const float* __restrict__ comb) {
    int t = blockIdx.x * blockDim.x + threadIdx.x;
    if (t >= NCHUNK * COUT_) return;
    int kc = t >> 8;                 // = nf
    int o  = t & 255;
    const float* src = comb + (size_t)o * K_ + kc;   // stride 16 floats over cin
    #pragma unroll
    for (int g = 0; g < 8; g++) {
        uint4 u;
        u.x = pack_h2(src[(g * 8 + 0) * NF_], src[(g * 8 + 1) * NF_]);
        u.y = pack_h2(src[(g * 8 + 2) * NF_], src[(g * 8 + 3) * NF_]);
        u.z = pack_h2(src[(g * 8 + 4) * NF_], src[(g * 8 + 5) * NF_]);
        u.w = pack_h2(src[(g * 8 + 6) * NF_], src[(g * 8 + 7) * NF_]);
        g_combB[(kc * COUT_ + o) * 8 + (g ^ (o & 7))] = u;
    }
}

// ---------------- fused warp-specialized kernel ----------------
__global__ __launch_bounds__(NTHREADS, 1)
void mma_kernel(const float* __restrict__ bias, float* __restrict__ out) {
    extern __shared__ char smem[];
    const uint32_t sb = smem_u32(smem);
    const int tx   = threadIdx.x;
    const int wid  = tx >> 5;
    const int lane = tx & 31;
    const int m0   = blockIdx.x * MT;

    if (tx == 0) {
        #pragma unroll
        for (int s = 0; s < NSTAGE; s++) {
            MBARRIER_INIT(sb + s * 8, 128);       // full
            MBARRIER_INIT(sb + 32 + s * 8, 128);  // empty
        }
    }
    __syncthreads();

    if (wid >= 4) {
        // ================= PRODUCER (warps 4-7) =================
        const int pt = tx - 128;          // 0..127
        const int wp = pt >> 5;           // 0..3
        const int u  = lane >> 4;         // pixel unit 0/1
        const int L  = lane & 15;         // cin quad

        const char* xrow[8];
        int         pp[8];
        uint32_t    sAoff[8];
        #pragma unroll
        for (int j = 0; j < 8; j++) {
            int ml = wp * 16 + j * 2 + u;
            int m  = m0 + ml;
            int b  = m / HW_;
            int p  = m - b * HW_;
            xrow[j]  = (const char*)g_xT + (size_t)b * (HW_ * CIN_ * 2) + L * 8;
            pp[j]    = p;
            sAoff[j] = (uint32_t)(ml * 128) + (((uint32_t)(L * 8)) ^ ((uint32_t)(ml & 7) << 4));
        }

        #pragma unroll 1
        for (int kc = 0; kc < NCHUNK; kc++) {
            const int s = kc & 3;
            if (kc >= NSTAGE)
                MBARRIER_WAIT_PARITY(sb + 32 + s * 8, ((kc - NSTAGE) >> 2) & 1);

            // ---- B: cp.async pre-swizzled image (32KB over 128 threads) ----
            {
                const char* bsrc = (const char*)g_combB + (size_t)kc * 32768;
                uint32_t bdst = sb + OFF_B + s * 32768;
                #pragma unroll
                for (int i = 0; i < 16; i++)
                    cp16(bdst + (pt + i * 128) * 16, bsrc + (size_t)(pt + i * 128) * 16);
                asm volatile("cp.async.commit_group;" ::: "memory");
            }

            // ---- A: coalesced gathers from xT, one nf per chunk ----
            {
                char* aB = smem + OFF_A + s * 8192;
                const uint4*  tO = g_tapO4 + kc * HW_;
                const float4* tW = g_tapW4 + kc * HW_;
                #pragma unroll
                for (int j = 0; j < 8; j++) {
                    uint4  o4 = __ldg(tO + pp[j]);
                    float4 w4 = __ldg(tW + pp[j]);
                    const char* xb = xrow[j];
                    uint2 d0 = *(const uint2*)(xb + o4.x);
                    uint2 d1 = *(const uint2*)(xb + o4.y);
                    uint2 d2 = *(const uint2*)(xb + o4.z);
                    uint2 d3 = *(const uint2*)(xb + o4.w);
                    float2 t0a = __half22float2(*(const __half2*)&d0.x);
                    float2 t0b = __half22float2(*(const __half2*)&d0.y);
                    float2 t1a = __half22float2(*(const __half2*)&d1.x);
                    float2 t1b = __half22float2(*(const __half2*)&d1.y);
                    float2 t2a = __half22float2(*(const __half2*)&d2.x);
                    float2 t2b = __half22float2(*(const __half2*)&d2.y);
                    float2 t3a = __half22float2(*(const __half2*)&d3.x);
                    float2 t3b = __half22float2(*(const __half2*)&d3.y);
                    float v0 = t0a.x * w4.x;
                    v0 = fmaf(t1a.x, w4.y, v0);
                    v0 = fmaf(t2a.x, w4.z, v0);
                    v0 = fmaf(t3a.x, w4.w, v0);
                    float v1 = t0a.y * w4.x;
                    v1 = fmaf(t1a.y, w4.y, v1);
                    v1 = fmaf(t2a.y, w4.z, v1);
                    v1 = fmaf(t3a.y, w4.w, v1);
                    float v2 = t0b.x * w4.x;
                    v2 = fmaf(t1b.x, w4.y, v2);
                    v2 = fmaf(t2b.x, w4.z, v2);
                    v2 = fmaf(t3b.x, w4.w, v2);
                    float v3 = t0b.y * w4.x;
                    v3 = fmaf(t1b.y, w4.y, v3);
                    v3 = fmaf(t2b.y, w4.z, v3);
                    v3 = fmaf(t3b.y, w4.w, v3);
                    uint32_t lo = pack_h2(v0, v1);
                    uint32_t hi = pack_h2(v2, v3);
                    *(uint2*)(aB + sAoff[j]) = make_uint2(lo, hi);
                }
            }

            asm volatile("cp.async.wait_group 0;" ::: "memory");
            MBARRIER_ARRIVE(sb + s * 8);
        }
    } else {
        // ================= CONSUMER (warps 0-3) =================
        const int w = wid;                // N slice [w*64, w*64+64)
        float acc[4][8][4];
        #pragma unroll
        for (int i = 0; i < 4; i++)
            #pragma unroll
            for (int j = 0; j < 8; j++)
                #pragma unroll
                for (int q = 0; q < 4; q++) acc[i][j][q] = 0.f;

        auto lm_addr = [&](uint32_t base, int rowBase, int kByte) -> uint32_t {
            int r  = rowBase + (lane & 7) + 8 * ((lane >> 3) & 1);
            int cb = kByte + 16 * (lane >> 4);
            return base + r * 128 + (uint32_t)(cb ^ ((r & 7) << 4));
        };

        #pragma unroll 1
        for (int kc = 0; kc < NCHUNK; kc++) {
            const int s = kc & 3;
            MBARRIER_WAIT_PARITY(sb + s * 8, (kc >> 2) & 1);
            const uint32_t aBuf = sb + OFF_A + s * 8192;
            const uint32_t bBuf = sb + OFF_B + s * 32768;

            #pragma unroll
            for (int ks = 0; ks < 4; ks++) {
                const int kB = ks * 32;
                uint32_t bb[4][4];
                #pragma unroll
                for (int jn = 0; jn < 4; jn++)
                    ldsm_x4(bb[jn][0], bb[jn][1], bb[jn][2], bb[jn][3],
                            lm_addr(bBuf, w * 64 + jn * 16, kB));
                #pragma unroll
                for (int wm = 0; wm < 4; wm++) {
                    uint32_t a0, a1, a2, a3;
                    ldsm_x4(a0, a1, a2, a3, lm_addr(aBuf, wm * 16, kB));
                    #pragma unroll
                    for (int jn = 0; jn < 4; jn++) {
                        mma_f16(acc[wm][jn * 2 + 0], a0, a1, a2, a3, bb[jn][0], bb[jn][2]);
                        mma_f16(acc[wm][jn * 2 + 1], a0, a1, a2, a3, bb[jn][1], bb[jn][3]);
                    }
                }
            }
            MBARRIER_ARRIVE(sb + 32 + s * 8);
        }

        // ---- epilogue ----
        const int r = lane >> 2;
        const int c = lane & 3;
        #pragma unroll
        for (int wm = 0; wm < 4; wm++) {
            int mr0 = m0 + wm * 16 + r;
            int mr1 = mr0 + 8;
            int b0i = mr0 / HW_, p0 = mr0 - b0i * HW_;
            int b1i = mr1 / HW_, p1 = mr1 - b1i * HW_;
            float* o0 = out + (size_t)b0i * COUT_ * HW_ + p0;
            float* o1 = out + (size_t)b1i * COUT_ * HW_ + p1;
            #pragma unroll
            for (int j = 0; j < 8; j++) {
                int n0 = w * 64 + (j >> 1) * 16 + (j & 1) * 8 + 2 * c;
                float bz0 = __ldg(bias + n0), bz1 = __ldg(bias + n0 + 1);
                o0[(size_t)n0 * HW_]       = acc[wm][j][0] + bz0;
                o0[(size_t)(n0 + 1) * HW_] = acc[wm][j][1] + bz1;
                o1[(size_t)n0 * HW_]       = acc[wm][j][2] + bz0;
                o1[(size_t)(n0 + 1) * HW_] = acc[wm][j][3] + bz1;
            }
        }
    }
}

extern "C" void kernel_launch(void* const* d_in, const int* in_sizes, int n_in,
                              void* d_out, int out_size) {
    const float* x    = (const float*)d_in[0];
    const float* flow = (const float*)d_in[1];
    const float* comb = (const float*)d_in[2];
    const float* bias = (const float*)d_in[3];
    float* out = (float*)d_out;

    cudaFuncSetAttribute(mma_kernel,
                         cudaFuncAttributeMaxDynamicSharedMemorySize, SMEM_TOTAL);

    xt_kernel<<<(B_ * HW_ + 127) / 128, 128>>>(x);
    tap_kernel<<<(NF_ * HW_ + 255) / 256, 256>>>(flow);
    comb_prep<<<(NCHUNK * COUT_ + 255) / 256, 256>>>(comb);
    mma_kernel<<<M_ / MT, NTHREADS, SMEM_TOTAL>>>(bias, out);
}